// round 10
// baseline (speedup 1.0000x reference)
#include <cuda_runtime.h>
#include <cuda_fp16.h>
#include <math.h>

#define NB   4
#define NN   15135
#define FIN0 8
#define HH   64
#define NE   302700
#define ETOT (NE + NN)
#define FCN  256
#define NL   3
#define SLOPE 0.2f
#define RT   74
#define RPB  205                   // 74*205 = 15170 >= NN
#define NROWS (NB * NN)            // 60540
#define NROWS_PAD (NROWS + 16)

// ---------------------------------------------------------------------------
// Static device scratch.  h layout: [node][batch][ch] half (512 B / node).
// ---------------------------------------------------------------------------
__device__ __half g_hA16[(size_t)NROWS_PAD * HH];
__device__ __half g_hB16[(size_t)NROWS_PAD * HH];
__device__ __half g_Wt[2][HH * HH];        // W1^T, W2^T fp16 ([c][f])
__device__ float g_es4[NL][NN * NB];
__device__ float g_ed4[NL][NN * NB];
__device__ float g_scores[NB * NN];
__device__ float g_h1part[RT * NB * FCN];
__device__ float g_wa[NL][2][HH];
__device__ int   g_cnt[NN];
__device__ int   g_rowptr[NN + 1];
__device__ int   g_wp[NN];
__device__ int   g_srcs[ETOT];

__device__ __forceinline__ __half* selbuf16(int s) { return s ? g_hB16 : g_hA16; }

// ---------------------------------------------------------------------------
// Prologue: init g_cnt, precompute W@a vectors, build fp16 W^T for mma
// ---------------------------------------------------------------------------
__global__ void k_pre(const float* __restrict__ W0, const float* __restrict__ as0, const float* __restrict__ ad0,
                      const float* __restrict__ W1, const float* __restrict__ as1, const float* __restrict__ ad1,
                      const float* __restrict__ W2, const float* __restrict__ as2, const float* __restrict__ ad2) {
    int i = blockIdx.x * blockDim.x + threadIdx.x;
    if (i < NN) g_cnt[i] = 1;
    if (blockIdx.x == 0 && threadIdx.x < HH) {
        int f = threadIdx.x;
        if (f < FIN0) {
            float s = 0.f, d = 0.f;
            for (int h = 0; h < HH; h++) { s += W0[f * HH + h] * as0[h]; d += W0[f * HH + h] * ad0[h]; }
            g_wa[0][0][f] = s; g_wa[0][1][f] = d;
        }
        float s1 = 0.f, d1 = 0.f, s2 = 0.f, d2 = 0.f;
        for (int h = 0; h < HH; h++) {
            s1 += W1[f * HH + h] * as1[h]; d1 += W1[f * HH + h] * ad1[h];
            s2 += W2[f * HH + h] * as2[h]; d2 += W2[f * HH + h] * ad2[h];
        }
        g_wa[1][0][f] = s1; g_wa[1][1][f] = d1;
        g_wa[2][0][f] = s2; g_wa[2][1][f] = d2;
    }
    if (blockIdx.x == 1 || blockIdx.x == 2) {
        const float* W = (blockIdx.x == 1) ? W1 : W2;
        __half* Wt = g_Wt[blockIdx.x - 1];
        for (int e = threadIdx.x; e < HH * HH; e += blockDim.x) {
            int c = e / HH, f = e % HH;           // Wt[c][f] = W[f][c]
            Wt[e] = __float2half(W[f * HH + c]);
        }
    }
}

__global__ void k_hist(const int* __restrict__ dst) {
    int i = blockIdx.x * blockDim.x + threadIdx.x;
    if (i < NE) atomicAdd(&g_cnt[dst[i]], 1);
}

__global__ void k_scan() {
    __shared__ int ssum[1024];
    int t = threadIdx.x;
    const int CH = (NN + 1023) / 1024;
    int base = t * CH;
    int loc[CH];
    int s = 0;
#pragma unroll
    for (int i = 0; i < CH; i++) {
        int idx = base + i;
        int v = (idx < NN) ? g_cnt[idx] : 0;
        loc[i] = s;
        s += v;
    }
    ssum[t] = s;
    __syncthreads();
    for (int off = 1; off < 1024; off <<= 1) {
        int add = (t >= off) ? ssum[t - off] : 0;
        __syncthreads();
        ssum[t] += add;
        __syncthreads();
    }
    int pre = ssum[t] - s;
#pragma unroll
    for (int i = 0; i < CH; i++) {
        int idx = base + i;
        if (idx < NN) {
            int v = pre + loc[i];
            g_rowptr[idx] = v;
            g_wp[idx] = v;
        }
    }
    if (t == 1023) g_rowptr[NN] = ssum[1023];
}

__global__ void k_scatter(const int* __restrict__ src, const int* __restrict__ dst) {
    int i = blockIdx.x * blockDim.x + threadIdx.x;
    if (i >= ETOT) return;
    int s, d;
    if (i < NE) { s = src[i]; d = dst[i]; }
    else        { s = d = i - NE; }
    int pos = atomicAdd(&g_wp[d], 1);
    g_srcs[pos] = s;
}

// ---------------------------------------------------------------------------
// Layer 0: h0[node][b][c] = x @ W0 (fp16), es0/ed0 interleaved
// ---------------------------------------------------------------------------
__global__ void k_lin0(const float* __restrict__ x, const float* __restrict__ W) {
    __shared__ float sW[FIN0 * HH];
    __shared__ float sx[16][FIN0];
    __shared__ float swa[2][FIN0];

    int tid = threadIdx.x;
    for (int i = tid; i < FIN0 * HH; i += 256) sW[i] = W[i];
    if (tid < 2 * FIN0) swa[tid / FIN0][tid % FIN0] = g_wa[0][tid / FIN0][tid % FIN0];

    int bn0 = blockIdx.x * 16;
    for (int i = tid; i < 16 * FIN0; i += 256) {
        int bn = bn0 + i / FIN0;
        sx[i / FIN0][i % FIN0] = (bn < NROWS) ? x[(size_t)bn * FIN0 + (i % FIN0)] : 0.f;
    }
    __syncthreads();

    int g = tid >> 6, c = tid & 63;
#pragma unroll
    for (int jj = 0; jj < 4; jj++) {
        int gg = g + jj * 4;
        int bn = bn0 + gg;
        float acc = 0.f;
#pragma unroll
        for (int f = 0; f < FIN0; f++) acc += sx[gg][f] * sW[f * HH + c];
        if (bn < NROWS) {
            int b = bn / NN, node = bn - b * NN;
            g_hA16[((size_t)node * NB + b) * HH + c] = __float2half(acc);
        }
    }

    if (tid < 32) {
        int j = tid >> 1, sel = tid & 1;
        int bn = bn0 + j;
        if (bn < NROWS) {
            float s = 0.f;
#pragma unroll
            for (int f = 0; f < FIN0; f++) s += sx[j][f] * swa[sel][f];
            int b = bn / NN, node = bn - b * NN;
            if (sel == 0) g_es4[0][node * NB + b] = s;
            else          g_ed4[0][node * NB + b] = s;
        }
    }
}

// ---------------------------------------------------------------------------
// Aggregation, no max pass (shift-invariant; logits O(10) << fp32 exp range).
// CHUNK PREFETCH: 32 srcs loaded coalesced per chunk, distributed by shfl, so
// per-edge es/h loads have no serial address chain (full MLP).
// One warp per node; lane = (batch = lane>>3, 8 channels).
// ---------------------------------------------------------------------------
template <bool LAST>
__global__ void k_agg(int insel, int layer,
                      const float* __restrict__ bvec,
                      const float* __restrict__ fcw) {
    int tid = threadIdx.x;
    int node = (blockIdx.x * blockDim.x + tid) >> 5;
    int lane = tid & 31;
    if (node >= NN) return;

    int myb = lane >> 3;
    int mych = (lane & 7) * 8;

    const float* esl = g_es4[layer];
    int beg = g_rowptr[node], end = g_rowptr[node + 1];
    float edv = g_ed4[layer][node * NB + myb];

    const uint4* hb = (const uint4*)selbuf16(insel);
    float acc[8];
#pragma unroll
    for (int k = 0; k < 8; k++) acc[k] = 0.f;
    float den = 0.f;

    for (int c0 = beg; c0 < end; c0 += 32) {
        int rem = end - c0;
        int cnt = rem < 32 ? rem : 32;
        int sreg = __ldg(&g_srcs[c0 + (lane < rem ? lane : 0)]);
#pragma unroll 4
        for (int j = 0; j < cnt; j++) {
            int s = __shfl_sync(0xffffffffu, sreg, j);
            float v = __ldg(&esl[s * NB + myb]) + edv;
            v = (v > 0.f) ? v : SLOPE * v;
            float ex = __expf(v);
            den += ex;
            uint4 hv = __ldg(&hb[(size_t)s * 32 + lane]);
            float2 p0 = __half22float2(*(__half2*)&hv.x);
            float2 p1 = __half22float2(*(__half2*)&hv.y);
            float2 p2 = __half22float2(*(__half2*)&hv.z);
            float2 p3 = __half22float2(*(__half2*)&hv.w);
            acc[0] += ex * p0.x; acc[1] += ex * p0.y;
            acc[2] += ex * p1.x; acc[3] += ex * p1.y;
            acc[4] += ex * p2.x; acc[5] += ex * p2.y;
            acc[6] += ex * p3.x; acc[7] += ex * p3.y;
        }
    }

    float inv = 1.f / den;
    float4 bb0 = __ldg((const float4*)(bvec + mych));
    float4 bb1 = __ldg((const float4*)(bvec + mych + 4));
    float o[8];
    o[0] = acc[0] * inv + bb0.x; o[1] = acc[1] * inv + bb0.y;
    o[2] = acc[2] * inv + bb0.z; o[3] = acc[3] * inv + bb0.w;
    o[4] = acc[4] * inv + bb1.x; o[5] = acc[5] * inv + bb1.y;
    o[6] = acc[6] * inv + bb1.z; o[7] = acc[7] * inv + bb1.w;
#pragma unroll
    for (int k = 0; k < 8; k++) o[k] = (o[k] > 0.f) ? o[k] : 0.f;

    // score contribution: feature index = ch*NL + layer
    {
        float sc = 0.f;
#pragma unroll
        for (int k = 0; k < 8; k++) sc += o[k] * __ldg(&fcw[(mych + k) * NL + layer]);
#pragma unroll
        for (int off = 4; off; off >>= 1)
            sc += __shfl_xor_sync(0xffffffffu, sc, off);
        if ((lane & 7) == 0) {
            if (layer == 0) g_scores[myb * NN + node] = sc;
            else            g_scores[myb * NN + node] += sc;
        }
    }

    if (!LAST) {
        int nl = layer + 1;
        float se = 0.f, sd = 0.f;
#pragma unroll
        for (int k = 0; k < 8; k++) {
            se += o[k] * g_wa[nl][0][mych + k];
            sd += o[k] * g_wa[nl][1][mych + k];
        }
#pragma unroll
        for (int off = 4; off; off >>= 1) {
            se += __shfl_xor_sync(0xffffffffu, se, off);
            sd += __shfl_xor_sync(0xffffffffu, sd, off);
        }
        if ((lane & 7) == 0) {
            g_es4[nl][node * NB + myb] = se;
            g_ed4[nl][node * NB + myb] = sd;
        }
        uint4 ov;
        ((__half2*)&ov)[0] = __floats2half2_rn(o[0], o[1]);
        ((__half2*)&ov)[1] = __floats2half2_rn(o[2], o[3]);
        ((__half2*)&ov)[2] = __floats2half2_rn(o[4], o[5]);
        ((__half2*)&ov)[3] = __floats2half2_rn(o[6], o[7]);
        ((uint4*)selbuf16(insel ^ 1))[((size_t)node * NB + myb) * 8 + (lane & 7)] = ov;
    }
}

// ---------------------------------------------------------------------------
// H_next = O @ W via mma.sync m16n8k16 (fp16 in, fp32 acc).
// ---------------------------------------------------------------------------
__global__ void __launch_bounds__(128, 1) k_gemm(int isel, int osel, int wsel) {
    const __half* O  = selbuf16(isel);
    __half* Hn = selbuf16(osel);
    const __half* Wt = g_Wt[wsel];
    int warp = (blockIdx.x * blockDim.x + threadIdx.x) >> 5;
    int lane = threadIdx.x & 31;
    int rbase = warp * 16;
    if (rbase >= NROWS) return;
    int t = lane & 3, g = lane >> 2;
    int row0 = rbase + g, row1 = row0 + 8;

    unsigned a[4][4];
#pragma unroll
    for (int kc = 0; kc < 4; kc++) {
        int k0 = kc * 16 + 2 * t;
        a[kc][0] = *(const unsigned*)&O[(size_t)row0 * HH + k0];
        a[kc][1] = *(const unsigned*)&O[(size_t)row1 * HH + k0];
        a[kc][2] = *(const unsigned*)&O[(size_t)row0 * HH + k0 + 8];
        a[kc][3] = *(const unsigned*)&O[(size_t)row1 * HH + k0 + 8];
    }
#pragma unroll
    for (int nt = 0; nt < 8; nt++) {
        int n = nt * 8 + g;
        float c0 = 0.f, c1 = 0.f, c2 = 0.f, c3 = 0.f;
#pragma unroll
        for (int kc = 0; kc < 4; kc++) {
            int k0 = kc * 16 + 2 * t;
            unsigned b0 = *(const unsigned*)&Wt[n * HH + k0];
            unsigned b1 = *(const unsigned*)&Wt[n * HH + k0 + 8];
            asm volatile(
                "mma.sync.aligned.m16n8k16.row.col.f32.f16.f16.f32 "
                "{%0,%1,%2,%3}, {%4,%5,%6,%7}, {%8,%9}, {%0,%1,%2,%3};\n"
                : "+f"(c0), "+f"(c1), "+f"(c2), "+f"(c3)
                : "r"(a[kc][0]), "r"(a[kc][1]), "r"(a[kc][2]), "r"(a[kc][3]),
                  "r"(b0), "r"(b1));
        }
        int col = nt * 8 + 2 * t;
        if (row0 < NROWS) *(__half2*)&Hn[(size_t)row0 * HH + col] = __floats2half2_rn(c0, c1);
        if (row1 < NROWS) *(__half2*)&Hn[(size_t)row1 * HH + col] = __floats2half2_rn(c2, c3);
    }
}

// ---------------------------------------------------------------------------
// Partial (scores+fcb) @ lin1_w. grid (2 c-tiles, RT row tiles) = 148 blocks.
// ---------------------------------------------------------------------------
__global__ void k_final(const float* __restrict__ w1, const float* __restrict__ fcb) {
    int lane = threadIdx.x;
    int ty = threadIdx.y;
    int cb = blockIdx.x * 128 + lane * 4;
    int rt = blockIdx.y;
    int n0 = rt * RPB;
    int n1 = min(NN, n0 + RPB);
    float f0 = fcb[0];

    float acc[NB][4];
#pragma unroll
    for (int b = 0; b < NB; b++)
#pragma unroll
        for (int j = 0; j < 4; j++) acc[b][j] = 0.f;

    for (int n = n0 + ty; n < n1; n += 8) {
        float4 w = __ldg((const float4*)&w1[(size_t)n * FCN + cb]);
        float sc[NB];
#pragma unroll
        for (int b = 0; b < NB; b++) sc[b] = g_scores[b * NN + n] + f0;
#pragma unroll
        for (int b = 0; b < NB; b++) {
            acc[b][0] += sc[b] * w.x;
            acc[b][1] += sc[b] * w.y;
            acc[b][2] += sc[b] * w.z;
            acc[b][3] += sc[b] * w.w;
        }
    }

    __shared__ float sh[8][32][16];
#pragma unroll
    for (int b = 0; b < NB; b++)
#pragma unroll
        for (int j = 0; j < 4; j++) sh[ty][lane][b * 4 + j] = acc[b][j];
    __syncthreads();

    int t = ty * 32 + lane;
#pragma unroll
    for (int q = t; q < 512; q += 256) {
        int ln = q >> 4, idx = q & 15;
        int b = idx >> 2, j = idx & 3;
        float s = 0.f;
#pragma unroll
        for (int k = 0; k < 8; k++) s += sh[k][ln][idx];
        g_h1part[(size_t)rt * NB * FCN + b * FCN + blockIdx.x * 128 + ln * 4 + j] = s;
    }
}

// ---------------------------------------------------------------------------
// Reduce partials, relu, lin2, log_softmax. One block, 256 threads.
// ---------------------------------------------------------------------------
__global__ void k_head(const float* __restrict__ b1v,
                       const float* __restrict__ w2, const float* __restrict__ b2v,
                       float* __restrict__ out) {
    __shared__ float h1s[NB][FCN];
    int tid = threadIdx.x;
    {
        int c = tid;
        float s[NB] = {0.f, 0.f, 0.f, 0.f};
        for (int rt = 0; rt < RT; rt++) {
            const float* p = g_h1part + (size_t)rt * NB * FCN;
#pragma unroll
            for (int b = 0; b < NB; b++) s[b] += p[b * FCN + c];
        }
        float bb = b1v[c];
#pragma unroll
        for (int b = 0; b < NB; b++) {
            float v = s[b] + bb;
            h1s[b][c] = (v > 0.f) ? v : 0.f;
        }
    }
    __syncthreads();

    int w = tid >> 5, lane = tid & 31;
    __shared__ float lg[NB][2];
    if (w < NB * 2) {
        int b = w >> 1, cls = w & 1;
        float acc = 0.f;
        for (int j = lane; j < FCN; j += 32)
            acc += h1s[b][j] * w2[j * 2 + cls];
        for (int off = 16; off; off >>= 1)
            acc += __shfl_xor_sync(0xffffffffu, acc, off);
        if (lane == 0) lg[b][cls] = acc + b2v[cls];
    }
    __syncthreads();
    if (tid < NB) {
        float l0 = lg[tid][0], l1 = lg[tid][1];
        float mm = fmaxf(l0, l1);
        float lse = mm + logf(__expf(l0 - mm) + __expf(l1 - mm));
        out[tid * 2 + 0] = l0 - lse;
        out[tid * 2 + 1] = l1 - lse;
    }
}

// ---------------------------------------------------------------------------
// Launch
// ---------------------------------------------------------------------------
extern "C" void kernel_launch(void* const* d_in, const int* in_sizes, int n_in,
                              void* d_out, int out_size) {
    const float* x   = (const float*)d_in[0];
    const int*   ei  = (const int*)d_in[1];
    const float* W0  = (const float*)d_in[3];
    const float* as0 = (const float*)d_in[4];
    const float* ad0 = (const float*)d_in[5];
    const float* b0  = (const float*)d_in[6];
    const float* W1  = (const float*)d_in[7];
    const float* as1 = (const float*)d_in[8];
    const float* ad1 = (const float*)d_in[9];
    const float* b1  = (const float*)d_in[10];
    const float* W2  = (const float*)d_in[11];
    const float* as2 = (const float*)d_in[12];
    const float* ad2 = (const float*)d_in[13];
    const float* b2  = (const float*)d_in[14];
    const float* fcw = (const float*)d_in[15];
    const float* fcb = (const float*)d_in[16];
    const float* l1w = (const float*)d_in[17];
    const float* l1b = (const float*)d_in[18];
    const float* l2w = (const float*)d_in[19];
    const float* l2b = (const float*)d_in[20];
    float* out = (float*)d_out;

    const int* srcp = ei;
    const int* dstp = ei + NE;

    k_pre<<<(NN + 255) / 256, 256>>>(W0, as0, ad0, W1, as1, ad1, W2, as2, ad2);
    k_hist<<<(NE + 255) / 256, 256>>>(dstp);
    k_scan<<<1, 1024>>>();
    k_scatter<<<(ETOT + 255) / 256, 256>>>(srcp, dstp);

    k_lin0<<<(NROWS + 15) / 16, 256>>>(x, W0);

    const int aggGrid = (NN * 32 + 255) / 256;
    const int gemmGrid = ((NROWS + 15) / 16 + 3) / 4;

    k_agg<false><<<aggGrid, 256>>>(/*in*/0, 0, b0, fcw);   // reads A, o -> B
    k_gemm<<<gemmGrid, 128>>>(1, 0, 0);                    // B @ W1 -> A
    k_agg<false><<<aggGrid, 256>>>(/*in*/0, 1, b1, fcw);   // reads A, o -> B
    k_gemm<<<gemmGrid, 128>>>(1, 0, 1);                    // B @ W2 -> A
    k_agg<true ><<<aggGrid, 256>>>(/*in*/0, 2, b2, fcw);   // reads A

    k_final<<<dim3(2, RT), dim3(32, 8)>>>(l1w, fcb);
    k_head<<<1, 256>>>(l1b, l2w, l2b, out);
}

// round 11
// speedup vs baseline: 1.0371x; 1.0371x over previous
#include <cuda_runtime.h>
#include <cuda_fp16.h>
#include <math.h>

#define NB   4
#define NN   15135
#define FIN0 8
#define HH   64
#define NE   302700
#define ETOT (NE + NN)
#define FCN  256
#define NL   3
#define SLOPE 0.2f
#define RT   74
#define RPB  205                   // 74*205 = 15170 >= NN
#define NROWS (NB * NN)            // 60540
#define NROWS_PAD (NROWS + 16)
#define CSRB 256                   // blocks in the fused CSR kernel
#define CPB  60                    // nodes per CSR block (256*60 >= NN)

// ---------------------------------------------------------------------------
// Static device scratch.  h layout: [node][batch][ch] half (512 B / node).
// ---------------------------------------------------------------------------
__device__ __half g_hA16[(size_t)NROWS_PAD * HH];
__device__ __half g_hB16[(size_t)NROWS_PAD * HH];
__device__ __half g_Wt[2][HH * HH];        // W1^T, W2^T fp16 ([c][f])
__device__ float g_es4[NL][NN * NB];
__device__ float g_ed4[NL][NN * NB];
__device__ float g_scores[NB * NN];
__device__ float g_h1part[RT * NB * FCN];
__device__ float g_wa[NL][2][HH];
__device__ int   g_cnt[NN];                // zero-init; reset to 0 every exec
__device__ int   g_rowptr[NN + 1];
__device__ int   g_wp[NN];
__device__ int   g_srcs[ETOT];
__device__ unsigned g_bar;                 // monotonic grid-barrier counter
__device__ int   g_part[CSRB];
__device__ int   g_ppre[CSRB];

__device__ __forceinline__ __half* selbuf16(int s) { return s ? g_hB16 : g_hA16; }

// Monotonic grid barrier: never reset; per-exec arrivals are aligned groups of
// CSRB (4 barriers * 256 = 1024 per exec, multiple of 256 -> targets align).
__device__ __forceinline__ void gridbar() {
    __syncthreads();
    if (threadIdx.x == 0) {
        __threadfence();
        unsigned old = atomicAdd(&g_bar, 1u);
        unsigned target = old - (old & (CSRB - 1)) + CSRB;
        volatile unsigned* p = &g_bar;
        while (*p < target) { }
        __threadfence();
    }
    __syncthreads();
}

// ---------------------------------------------------------------------------
// Fused CSR build: histogram -> scan -> scatter in one kernel (grid barriers).
// g_cnt is read-(+1 self loop)-and-reset each exec, so no init pass needed.
// ---------------------------------------------------------------------------
__global__ void __launch_bounds__(256) k_csr(const int* __restrict__ src,
                                             const int* __restrict__ dst) {
    int tid = threadIdx.x, bid = blockIdx.x;
    int gt = bid * 256 + tid;

    // Phase A: histogram
    for (int i = gt; i < NE; i += CSRB * 256)
        atomicAdd(&g_cnt[dst[i]], 1);
    gridbar();

    // Phase B1: per-block chunk values (deg+1), reset cnt, block inclusive scan
    __shared__ int ss[64];
    int n0 = bid * CPB;
    int v = 0;
    if (tid < CPB) {
        int n = n0 + tid;
        if (n < NN) { v = g_cnt[n] + 1; g_cnt[n] = 0; }
    }
    if (tid < 64) ss[tid] = (tid < CPB) ? v : 0;
    __syncthreads();
    for (int off = 1; off < 64; off <<= 1) {
        int add = 0;
        if (tid < 64 && tid >= off) add = ss[tid - off];
        __syncthreads();
        if (tid < 64) ss[tid] += add;
        __syncthreads();
    }
    if (tid == 0) g_part[bid] = ss[63];
    gridbar();

    // Phase B2: block 0 scans the 256 partials
    if (bid == 0) {
        __shared__ int sp[CSRB];
        int pv = g_part[tid];
        sp[tid] = pv;
        __syncthreads();
        for (int off = 1; off < CSRB; off <<= 1) {
            int add = (tid >= off) ? sp[tid - off] : 0;
            __syncthreads();
            sp[tid] += add;
            __syncthreads();
        }
        g_ppre[tid] = sp[tid] - pv;          // exclusive prefix
        if (tid == CSRB - 1) g_rowptr[NN] = sp[CSRB - 1];
    }
    gridbar();

    // Phase B3: write rowptr / wp for this block's chunk
    int base = g_ppre[bid];
    if (tid < CPB) {
        int n = n0 + tid;
        if (n < NN) {
            int r = base + ss[tid] - v;      // exclusive within block
            g_rowptr[n] = r;
            g_wp[n] = r;
        }
    }
    gridbar();

    // Phase C: scatter (edges + self loops)
    for (int i = gt; i < ETOT; i += CSRB * 256) {
        int s, d;
        if (i < NE) { s = src[i]; d = dst[i]; }
        else        { s = d = i - NE; }
        int pos = atomicAdd(&g_wp[d], 1);
        g_srcs[pos] = s;
    }
}

// ---------------------------------------------------------------------------
// Misc prologue: wa for layers 1,2 + fp16 W^T for the mma kernels. 1 block.
// ---------------------------------------------------------------------------
__global__ void k_misc(const float* __restrict__ W1, const float* __restrict__ as1, const float* __restrict__ ad1,
                       const float* __restrict__ W2, const float* __restrict__ as2, const float* __restrict__ ad2) {
    int tid = threadIdx.x;
    if (tid < HH) {
        int f = tid;
        float s1 = 0.f, d1 = 0.f, s2 = 0.f, d2 = 0.f;
        for (int h = 0; h < HH; h++) {
            s1 += W1[f * HH + h] * as1[h]; d1 += W1[f * HH + h] * ad1[h];
            s2 += W2[f * HH + h] * as2[h]; d2 += W2[f * HH + h] * ad2[h];
        }
        g_wa[1][0][f] = s1; g_wa[1][1][f] = d1;
        g_wa[2][0][f] = s2; g_wa[2][1][f] = d2;
    }
    for (int e = tid; e < HH * HH; e += 256) {
        int c = e / HH, f = e % HH;           // Wt[c][f] = W[f][c]
        g_Wt[0][e] = __float2half(W1[f * HH + c]);
        g_Wt[1][e] = __float2half(W2[f * HH + c]);
    }
}

// ---------------------------------------------------------------------------
// Layer 0: h0[node][b][c] = x @ W0 (fp16), es0/ed0 interleaved.
// Self-contained: computes W0@a_src / W0@a_dst from its own smem copy of W0.
// ---------------------------------------------------------------------------
__global__ void k_lin0(const float* __restrict__ x, const float* __restrict__ W,
                       const float* __restrict__ as0, const float* __restrict__ ad0) {
    __shared__ float sW[FIN0 * HH];
    __shared__ float sx[16][FIN0];
    __shared__ float swa[2][FIN0];

    int tid = threadIdx.x;
    for (int i = tid; i < FIN0 * HH; i += 256) sW[i] = W[i];

    int bn0 = blockIdx.x * 16;
    for (int i = tid; i < 16 * FIN0; i += 256) {
        int bn = bn0 + i / FIN0;
        sx[i / FIN0][i % FIN0] = (bn < NROWS) ? x[(size_t)bn * FIN0 + (i % FIN0)] : 0.f;
    }
    __syncthreads();

    if (tid < 2 * FIN0) {
        int sel = tid >> 3, f = tid & 7;
        const float* a = sel ? ad0 : as0;
        float s = 0.f;
#pragma unroll
        for (int h = 0; h < HH; h++) s += sW[f * HH + h] * a[h];
        swa[sel][f] = s;
    }
    __syncthreads();

    int g = tid >> 6, c = tid & 63;
#pragma unroll
    for (int jj = 0; jj < 4; jj++) {
        int gg = g + jj * 4;
        int bn = bn0 + gg;
        float acc = 0.f;
#pragma unroll
        for (int f = 0; f < FIN0; f++) acc += sx[gg][f] * sW[f * HH + c];
        if (bn < NROWS) {
            int b = bn / NN, node = bn - b * NN;
            g_hA16[((size_t)node * NB + b) * HH + c] = __float2half(acc);
        }
    }

    if (tid < 32) {
        int j = tid >> 1, sel = tid & 1;
        int bn = bn0 + j;
        if (bn < NROWS) {
            float s = 0.f;
#pragma unroll
            for (int f = 0; f < FIN0; f++) s += sx[j][f] * swa[sel][f];
            int b = bn / NN, node = bn - b * NN;
            if (sel == 0) g_es4[0][node * NB + b] = s;
            else          g_ed4[0][node * NB + b] = s;
        }
    }
}

// ---------------------------------------------------------------------------
// Aggregation, no max pass (shift-invariant; logits O(10) << fp32 exp range).
// One warp per node; lane = (batch = lane>>3, 8 channels). r8-style loop.
// ---------------------------------------------------------------------------
template <bool LAST>
__global__ void k_agg(int insel, int layer,
                      const float* __restrict__ bvec,
                      const float* __restrict__ fcw) {
    int tid = threadIdx.x;
    int node = (blockIdx.x * blockDim.x + tid) >> 5;
    int lane = tid & 31;
    if (node >= NN) return;

    int myb = lane >> 3;
    int mych = (lane & 7) * 8;

    const float* esl = g_es4[layer];
    int beg = g_rowptr[node], end = g_rowptr[node + 1];
    float edv = g_ed4[layer][node * NB + myb];

    const uint4* hb = (const uint4*)selbuf16(insel);
    float acc[8];
#pragma unroll
    for (int k = 0; k < 8; k++) acc[k] = 0.f;
    float den = 0.f;

#pragma unroll 4
    for (int i = beg; i < end; i++) {
        int s = __ldg(&g_srcs[i]);
        float v = __ldg(&esl[s * NB + myb]) + edv;
        v = (v > 0.f) ? v : SLOPE * v;
        float ex = __expf(v);
        den += ex;
        uint4 hv = __ldg(&hb[(size_t)s * 32 + lane]);
        float2 p0 = __half22float2(*(__half2*)&hv.x);
        float2 p1 = __half22float2(*(__half2*)&hv.y);
        float2 p2 = __half22float2(*(__half2*)&hv.z);
        float2 p3 = __half22float2(*(__half2*)&hv.w);
        acc[0] += ex * p0.x; acc[1] += ex * p0.y;
        acc[2] += ex * p1.x; acc[3] += ex * p1.y;
        acc[4] += ex * p2.x; acc[5] += ex * p2.y;
        acc[6] += ex * p3.x; acc[7] += ex * p3.y;
    }

    float inv = 1.f / den;
    float4 bb0 = __ldg((const float4*)(bvec + mych));
    float4 bb1 = __ldg((const float4*)(bvec + mych + 4));
    float o[8];
    o[0] = acc[0] * inv + bb0.x; o[1] = acc[1] * inv + bb0.y;
    o[2] = acc[2] * inv + bb0.z; o[3] = acc[3] * inv + bb0.w;
    o[4] = acc[4] * inv + bb1.x; o[5] = acc[5] * inv + bb1.y;
    o[6] = acc[6] * inv + bb1.z; o[7] = acc[7] * inv + bb1.w;
#pragma unroll
    for (int k = 0; k < 8; k++) o[k] = (o[k] > 0.f) ? o[k] : 0.f;

    // score contribution: feature index = ch*NL + layer
    {
        float sc = 0.f;
#pragma unroll
        for (int k = 0; k < 8; k++) sc += o[k] * __ldg(&fcw[(mych + k) * NL + layer]);
#pragma unroll
        for (int off = 4; off; off >>= 1)
            sc += __shfl_xor_sync(0xffffffffu, sc, off);
        if ((lane & 7) == 0) {
            if (layer == 0) g_scores[myb * NN + node] = sc;
            else            g_scores[myb * NN + node] += sc;
        }
    }

    if (!LAST) {
        int nl = layer + 1;
        float se = 0.f, sd = 0.f;
#pragma unroll
        for (int k = 0; k < 8; k++) {
            se += o[k] * g_wa[nl][0][mych + k];
            sd += o[k] * g_wa[nl][1][mych + k];
        }
#pragma unroll
        for (int off = 4; off; off >>= 1) {
            se += __shfl_xor_sync(0xffffffffu, se, off);
            sd += __shfl_xor_sync(0xffffffffu, sd, off);
        }
        if ((lane & 7) == 0) {
            g_es4[nl][node * NB + myb] = se;
            g_ed4[nl][node * NB + myb] = sd;
        }
        uint4 ov;
        ((__half2*)&ov)[0] = __floats2half2_rn(o[0], o[1]);
        ((__half2*)&ov)[1] = __floats2half2_rn(o[2], o[3]);
        ((__half2*)&ov)[2] = __floats2half2_rn(o[4], o[5]);
        ((__half2*)&ov)[3] = __floats2half2_rn(o[6], o[7]);
        ((uint4*)selbuf16(insel ^ 1))[((size_t)node * NB + myb) * 8 + (lane & 7)] = ov;
    }
}

// ---------------------------------------------------------------------------
// H_next = O @ W via mma.sync m16n8k16 (fp16 in, fp32 acc).
// ---------------------------------------------------------------------------
__global__ void __launch_bounds__(128, 1) k_gemm(int isel, int osel, int wsel) {
    const __half* O  = selbuf16(isel);
    __half* Hn = selbuf16(osel);
    const __half* Wt = g_Wt[wsel];
    int warp = (blockIdx.x * blockDim.x + threadIdx.x) >> 5;
    int lane = threadIdx.x & 31;
    int rbase = warp * 16;
    if (rbase >= NROWS) return;
    int t = lane & 3, g = lane >> 2;
    int row0 = rbase + g, row1 = row0 + 8;

    unsigned a[4][4];
#pragma unroll
    for (int kc = 0; kc < 4; kc++) {
        int k0 = kc * 16 + 2 * t;
        a[kc][0] = *(const unsigned*)&O[(size_t)row0 * HH + k0];
        a[kc][1] = *(const unsigned*)&O[(size_t)row1 * HH + k0];
        a[kc][2] = *(const unsigned*)&O[(size_t)row0 * HH + k0 + 8];
        a[kc][3] = *(const unsigned*)&O[(size_t)row1 * HH + k0 + 8];
    }
#pragma unroll
    for (int nt = 0; nt < 8; nt++) {
        int n = nt * 8 + g;
        float c0 = 0.f, c1 = 0.f, c2 = 0.f, c3 = 0.f;
#pragma unroll
        for (int kc = 0; kc < 4; kc++) {
            int k0 = kc * 16 + 2 * t;
            unsigned b0 = *(const unsigned*)&Wt[n * HH + k0];
            unsigned b1 = *(const unsigned*)&Wt[n * HH + k0 + 8];
            asm volatile(
                "mma.sync.aligned.m16n8k16.row.col.f32.f16.f16.f32 "
                "{%0,%1,%2,%3}, {%4,%5,%6,%7}, {%8,%9}, {%0,%1,%2,%3};\n"
                : "+f"(c0), "+f"(c1), "+f"(c2), "+f"(c3)
                : "r"(a[kc][0]), "r"(a[kc][1]), "r"(a[kc][2]), "r"(a[kc][3]),
                  "r"(b0), "r"(b1));
        }
        int col = nt * 8 + 2 * t;
        if (row0 < NROWS) *(__half2*)&Hn[(size_t)row0 * HH + col] = __floats2half2_rn(c0, c1);
        if (row1 < NROWS) *(__half2*)&Hn[(size_t)row1 * HH + col] = __floats2half2_rn(c2, c3);
    }
}

// ---------------------------------------------------------------------------
// Partial (scores+fcb) @ lin1_w. grid (2 c-tiles, RT row tiles) = 148 blocks.
// ---------------------------------------------------------------------------
__global__ void k_final(const float* __restrict__ w1, const float* __restrict__ fcb) {
    int lane = threadIdx.x;
    int ty = threadIdx.y;
    int cb = blockIdx.x * 128 + lane * 4;
    int rt = blockIdx.y;
    int n0 = rt * RPB;
    int n1 = min(NN, n0 + RPB);
    float f0 = fcb[0];

    float acc[NB][4];
#pragma unroll
    for (int b = 0; b < NB; b++)
#pragma unroll
        for (int j = 0; j < 4; j++) acc[b][j] = 0.f;

    for (int n = n0 + ty; n < n1; n += 8) {
        float4 w = __ldg((const float4*)&w1[(size_t)n * FCN + cb]);
        float sc[NB];
#pragma unroll
        for (int b = 0; b < NB; b++) sc[b] = g_scores[b * NN + n] + f0;
#pragma unroll
        for (int b = 0; b < NB; b++) {
            acc[b][0] += sc[b] * w.x;
            acc[b][1] += sc[b] * w.y;
            acc[b][2] += sc[b] * w.z;
            acc[b][3] += sc[b] * w.w;
        }
    }

    __shared__ float sh[8][32][16];
#pragma unroll
    for (int b = 0; b < NB; b++)
#pragma unroll
        for (int j = 0; j < 4; j++) sh[ty][lane][b * 4 + j] = acc[b][j];
    __syncthreads();

    int t = ty * 32 + lane;
#pragma unroll
    for (int q = t; q < 512; q += 256) {
        int ln = q >> 4, idx = q & 15;
        int b = idx >> 2, j = idx & 3;
        float s = 0.f;
#pragma unroll
        for (int k = 0; k < 8; k++) s += sh[k][ln][idx];
        g_h1part[(size_t)rt * NB * FCN + b * FCN + blockIdx.x * 128 + ln * 4 + j] = s;
    }
}

// ---------------------------------------------------------------------------
// Reduce partials, relu, lin2, log_softmax. One block, 256 threads.
// ---------------------------------------------------------------------------
__global__ void k_head(const float* __restrict__ b1v,
                       const float* __restrict__ w2, const float* __restrict__ b2v,
                       float* __restrict__ out) {
    __shared__ float h1s[NB][FCN];
    int tid = threadIdx.x;
    {
        int c = tid;
        float s[NB] = {0.f, 0.f, 0.f, 0.f};
        for (int rt = 0; rt < RT; rt++) {
            const float* p = g_h1part + (size_t)rt * NB * FCN;
#pragma unroll
            for (int b = 0; b < NB; b++) s[b] += p[b * FCN + c];
        }
        float bb = b1v[c];
#pragma unroll
        for (int b = 0; b < NB; b++) {
            float v = s[b] + bb;
            h1s[b][c] = (v > 0.f) ? v : 0.f;
        }
    }
    __syncthreads();

    int w = tid >> 5, lane = tid & 31;
    __shared__ float lg[NB][2];
    if (w < NB * 2) {
        int b = w >> 1, cls = w & 1;
        float acc = 0.f;
        for (int j = lane; j < FCN; j += 32)
            acc += h1s[b][j] * w2[j * 2 + cls];
        for (int off = 16; off; off >>= 1)
            acc += __shfl_xor_sync(0xffffffffu, acc, off);
        if (lane == 0) lg[b][cls] = acc + b2v[cls];
    }
    __syncthreads();
    if (tid < NB) {
        float l0 = lg[tid][0], l1 = lg[tid][1];
        float mm = fmaxf(l0, l1);
        float lse = mm + logf(__expf(l0 - mm) + __expf(l1 - mm));
        out[tid * 2 + 0] = l0 - lse;
        out[tid * 2 + 1] = l1 - lse;
    }
}

// ---------------------------------------------------------------------------
// Launch.  Order chosen so the ncu capture slot (my 4th launch) hits k_agg L0.
// ---------------------------------------------------------------------------
extern "C" void kernel_launch(void* const* d_in, const int* in_sizes, int n_in,
                              void* d_out, int out_size) {
    const float* x   = (const float*)d_in[0];
    const int*   ei  = (const int*)d_in[1];
    const float* W0  = (const float*)d_in[3];
    const float* as0 = (const float*)d_in[4];
    const float* ad0 = (const float*)d_in[5];
    const float* b0  = (const float*)d_in[6];
    const float* W1  = (const float*)d_in[7];
    const float* as1 = (const float*)d_in[8];
    const float* ad1 = (const float*)d_in[9];
    const float* b1  = (const float*)d_in[10];
    const float* W2  = (const float*)d_in[11];
    const float* as2 = (const float*)d_in[12];
    const float* ad2 = (const float*)d_in[13];
    const float* b2  = (const float*)d_in[14];
    const float* fcw = (const float*)d_in[15];
    const float* fcb = (const float*)d_in[16];
    const float* l1w = (const float*)d_in[17];
    const float* l1b = (const float*)d_in[18];
    const float* l2w = (const float*)d_in[19];
    const float* l2b = (const float*)d_in[20];
    float* out = (float*)d_out;

    const int* srcp = ei;
    const int* dstp = ei + NE;

    const int aggGrid = (NN * 32 + 255) / 256;
    const int gemmGrid = ((NROWS + 15) / 16 + 3) / 4;

    k_lin0<<<(NROWS + 15) / 16, 256>>>(x, W0, as0, ad0);            // 1
    k_csr<<<CSRB, 256>>>(srcp, dstp);                               // 2
    k_misc<<<1, 256>>>(W1, as1, ad1, W2, as2, ad2);                 // 3
    k_agg<false><<<aggGrid, 256>>>(/*in*/0, 0, b0, fcw);            // 4 <- profiled
    k_gemm<<<gemmGrid, 128>>>(1, 0, 0);                             // 5
    k_agg<false><<<aggGrid, 256>>>(/*in*/0, 1, b1, fcw);            // 6
    k_gemm<<<gemmGrid, 128>>>(1, 0, 1);                             // 7
    k_agg<true ><<<aggGrid, 256>>>(/*in*/0, 2, b2, fcw);            // 8
    k_final<<<dim3(2, RT), dim3(32, 8)>>>(l1w, fcb);                // 9
    k_head<<<1, 256>>>(l1b, l2w, l2b, out);                         // 10
}